// round 1
// baseline (speedup 1.0000x reference)
#include <cuda_runtime.h>
#include <math.h>

// ---------------------------------------------------------------------------
// Pyramid scratch (device globals — no allocation allowed).
// tex0: base 128 (input), levels 1..7 (R=64..1) stored here.
// tex1: base 512 (input), levels 1..9 (R=256..1) stored here.
// Offsets are in float units; level 0 lives in the input buffer.
// ---------------------------------------------------------------------------
__device__ float g_pyr0[98304];
__device__ float g_pyr1[1572864];

__constant__ int c_OFF0[8]  = {0, 0, 73728, 92160, 96768, 97920, 98208, 98280};
__constant__ int c_OFF1[10] = {0, 0, 1179648, 1474560, 1548288, 1566720,
                               1571328, 1572480, 1572768, 1572840};

// one output texel of a 2x2-mean downsample
__device__ __forceinline__ void ds_one(const float* __restrict__ in,
                                       float* __restrict__ out,
                                       int Rout, int idx) {
    int x = idx % Rout;
    int y = (idx / Rout) % Rout;
    int f = idx / (Rout * Rout);
    int Rin = Rout << 1;
    const float* p = in + ((size_t)((f * Rin + 2 * y)) * Rin + 2 * x) * 3;
    const float* q = p + (size_t)Rin * 3;
    float* o = out + (size_t)idx * 3;
    o[0] = 0.25f * (p[0] + p[3] + q[0] + q[3]);
    o[1] = 0.25f * (p[1] + p[4] + q[1] + q[4]);
    o[2] = 0.25f * (p[2] + p[5] + q[2] + q[5]);
}

// big downsample levels (parallel across texels)
__global__ void ds_big(const float* __restrict__ in_base, int which, int lvl) {
    float* pyr       = which ? g_pyr1 : g_pyr0;
    const int* offs  = which ? c_OFF1 : c_OFF0;
    int baseR        = which ? 512 : 128;
    int Rout         = baseR >> lvl;
    const float* in  = (lvl == 1) ? in_base : (pyr + offs[lvl - 1]);
    float* out       = pyr + offs[lvl];
    int total        = 6 * Rout * Rout;
    int idx = blockIdx.x * blockDim.x + threadIdx.x;
    if (idx < total) ds_one(in, out, Rout, idx);
}

// fused small tail levels: block 0 -> pyr0 levels 2..7, block 1 -> pyr1 levels 4..9
__global__ void ds_tail() {
    int which        = blockIdx.x;
    float* pyr       = which ? g_pyr1 : g_pyr0;
    const int* offs  = which ? c_OFF1 : c_OFF0;
    int baseR        = which ? 512 : 128;
    int lstart       = which ? 4 : 2;
    int lmax         = which ? 9 : 7;
    for (int l = lstart; l <= lmax; l++) {
        int Rout = baseR >> l;
        int total = 6 * Rout * Rout;
        const float* in = pyr + offs[l - 1];
        float* out = pyr + offs[l];
        for (int idx = threadIdx.x; idx < total; idx += blockDim.x)
            ds_one(in, out, Rout, idx);
        __syncthreads();
    }
}

// bilinear fetch (matches reference weight order exactly)
__device__ __forceinline__ float3 bil(const float* __restrict__ t, int R,
                                      int face, float u, float v) {
    float x = u * (float)R - 0.5f;
    float y = v * (float)R - 0.5f;
    float x0f = floorf(x), y0f = floorf(y);
    float fx = x - x0f, fy = y - y0f;
    int xi = (int)x0f, yi = (int)y0f;
    int x0 = min(max(xi, 0), R - 1);
    int x1 = min(max(xi + 1, 0), R - 1);
    int y0 = min(max(yi, 0), R - 1);
    int y1 = min(max(yi + 1, 0), R - 1);
    const float* b = t + (size_t)face * R * R * 3;
    const float* p00 = b + ((size_t)y0 * R + x0) * 3;
    const float* p01 = b + ((size_t)y0 * R + x1) * 3;
    const float* p10 = b + ((size_t)y1 * R + x0) * 3;
    const float* p11 = b + ((size_t)y1 * R + x1) * 3;
    float w00 = (1.0f - fx) * (1.0f - fy);
    float w01 = fx * (1.0f - fy);
    float w10 = (1.0f - fx) * fy;
    float w11 = fx * fy;
    float3 r;
    r.x = w00 * __ldg(p00 + 0) + w01 * __ldg(p01 + 0) + w10 * __ldg(p10 + 0) + w11 * __ldg(p11 + 0);
    r.y = w00 * __ldg(p00 + 1) + w01 * __ldg(p01 + 1) + w10 * __ldg(p10 + 1) + w11 * __ldg(p11 + 1);
    r.z = w00 * __ldg(p00 + 2) + w01 * __ldg(p01 + 2) + w10 * __ldg(p10 + 2) + w11 * __ldg(p11 + 2);
    return r;
}

// trilinear sample from a full pyramid (base level in `base`, rest in `pyr`)
__device__ __forceinline__ float3 sample_pyr(const float* __restrict__ base,
                                             const float* __restrict__ pyr,
                                             const int* offs, int baseR,
                                             int lmax, float m,
                                             int face, float u, float v) {
    m = fminf(m, (float)lmax);           // m >= 0 guaranteed by caller
    int l0 = (int)m;
    float f = m - (float)l0;
    const float* t0 = (l0 == 0) ? base : (pyr + offs[l0]);
    float3 c = bil(t0, baseR >> l0, face, u, v);
    if (f > 0.0f) {
        int l1 = l0 + 1;                 // f>0 implies l0 < lmax
        float3 c1 = bil(pyr + offs[l1], baseR >> l1, face, u, v);
        float g = 1.0f - f;
        c.x = g * c.x + f * c1.x;
        c.y = g * c.y + f * c1.y;
        c.z = g * c.z + f * c1.z;
    }
    return c;
}

__global__ void sample_kernel(const float* __restrict__ vd,
                              const float* __restrict__ sa,
                              const float* __restrict__ nu,
                              const float* __restrict__ t0,
                              const float* __restrict__ t1,
                              const float* __restrict__ pbr,
                              const float* __restrict__ pmul,
                              const float* __restrict__ pmb,
                              float* __restrict__ out, int n) {
    int i = blockIdx.x * blockDim.x + threadIdx.x;
    if (i >= n) return;

    float vx = vd[3 * i + 0];
    float vy = vd[3 * i + 1];
    float vz = vd[3 * i + 2];
    float ax = fabsf(vx), ay = fabsf(vy), az = fabsf(vz);
    float ma = fmaxf(ax, fmaxf(ay, az));

    // miplevel = (saSample - log(distortion/(512*512))) / log(4) / 2 + mipbias + 0.5*noise
    float saTexel = (1.0f / ma) * (1.0f / (512.0f * 512.0f));
    float mip = (sa[i] - logf(saTexel)) * 0.36067376022224085f  // 1/(2*ln 4)
                + pmb[0] + 0.5f * nu[i];
    mip = fmaxf(mip, 0.0f);

    // cube face selection (matches reference)
    int face; float sc, tc, den;
    bool is_x = (ax >= ay) && (ax >= az);
    bool is_y = (!is_x) && (ay >= az);
    if (is_x)      { face = (vx >= 0.0f) ? 0 : 1; den = ax; sc = (vx >= 0.0f) ? -vz :  vz; tc = -vy; }
    else if (is_y) { face = (vy >= 0.0f) ? 2 : 3; den = ay; sc =  vx;                      tc = (vy >= 0.0f) ?  vz : -vz; }
    else           { face = (vz >= 0.0f) ? 4 : 5; den = az; sc = (vz >= 0.0f) ?  vx : -vx; tc = -vy; }
    float u = 0.5f * (sc / den + 1.0f);
    float v = 0.5f * (tc / den + 1.0f);

    float3 s0 = sample_pyr(t0, g_pyr0, c_OFF0, 128, 7, mip, face, u, v);
    float3 s1 = sample_pyr(t1, g_pyr1, c_OFF1, 512, 9, mip, face, u, v);

    float br  = fminf(fmaxf(pbr[0], -1.0f), 2.0f);
    float mul = pmul[0];
    float ox = fminf(fmaxf(expf(br + mul * (s0.x + s1.x)), 0.01f), 1000.0f);
    float oy = fminf(fmaxf(expf(br + mul * (s0.y + s1.y)), 0.01f), 1000.0f);
    float oz = fminf(fmaxf(expf(br + mul * (s0.z + s1.z)), 0.01f), 1000.0f);
    out[3 * i + 0] = ox;
    out[3 * i + 1] = oy;
    out[3 * i + 2] = oz;
}

extern "C" void kernel_launch(void* const* d_in, const int* in_sizes, int n_in,
                              void* d_out, int out_size) {
    const float* vd  = (const float*)d_in[0];  // viewdirs  [B,3]
    const float* sa  = (const float*)d_in[1];  // saSample  [B]
    const float* nu  = (const float*)d_in[2];  // noise_u   [B]
    const float* t0  = (const float*)d_in[3];  // bg_mat0   [1,6,128,128,3]
    const float* t1  = (const float*)d_in[4];  // bg_mat1   [1,6,512,512,3]
    const float* br  = (const float*)d_in[5];  // brightness scalar
    const float* mul = (const float*)d_in[6];  // mul scalar
    const float* mb  = (const float*)d_in[7];  // mipbias scalar
    int n = in_sizes[1];                       // B rays

    // pyramid build: 4 parallel downsample launches + 1 fused tail launch
    ds_big<<<(6 * 64 * 64 + 255) / 256, 256>>>(t0, 0, 1);     // 128 -> 64
    ds_big<<<(6 * 256 * 256 + 255) / 256, 256>>>(t1, 1, 1);   // 512 -> 256
    ds_big<<<(6 * 128 * 128 + 255) / 256, 256>>>(t1, 1, 2);   // 256 -> 128
    ds_big<<<(6 * 64 * 64 + 255) / 256, 256>>>(t1, 1, 3);     // 128 -> 64
    ds_tail<<<2, 1024>>>();                                   // all remaining levels

    sample_kernel<<<(n + 255) / 256, 256>>>(vd, sa, nu, t0, t1, br, mul, mb,
                                            (float*)d_out, n);
}

// round 2
// speedup vs baseline: 1.4416x; 1.4416x over previous
#include <cuda_runtime.h>
#include <math.h>

// ---------------------------------------------------------------------------
// Pyramid scratch (float4-padded texels; w unused). Level 0 stays in the
// float3 input buffers (cold path: mip >= ~3.5 in practice).
// ---------------------------------------------------------------------------
__device__ float4 g_p0[32766];    // tex0 levels 1..7  (R=64..1)
__device__ float4 g_p1[524286];   // tex1 levels 1..9  (R=256..1)

// offsets of level l (float4 units); index 0 unused
__constant__ int OFF0[8]  = {0, 0, 24576, 30720, 32256, 32640, 32736, 32760};
__constant__ int OFF1[10] = {0, 0, 393216, 491520, 516096, 522240,
                             523776, 524160, 524256, 524280};

// ---------------------------------------------------------------------------
// Build kernel 1: tex1 levels 1..3 in one pass (each thread owns one level-3
// texel = an 8x8 input block), plus tex0 level 1.
// ---------------------------------------------------------------------------
__global__ void build1(const float* __restrict__ t0, const float* __restrict__ t1) {
    int idx = blockIdx.x * blockDim.x + threadIdx.x;
    if (idx < 24576) {
        // ---- tex1: level-3 texel (x,y) of face f ----
        int x = idx & 63, y = (idx >> 6) & 63, f = idx >> 12;
        const float* in = t1 + (size_t)f * 512 * 512 * 3;
        float4* L1 = g_p1 + 0      + (size_t)f * 256 * 256;   // OFF1[1]=0
        float4* L2 = g_p1 + 393216 + (size_t)f * 128 * 128;
        float4* L3 = g_p1 + 491520 + (size_t)f * 64 * 64;

        float a2x[2][2] = {}, a2y[2][2] = {}, a2z[2][2] = {};
        #pragma unroll
        for (int sy = 0; sy < 4; sy++) {
            #pragma unroll
            for (int sx = 0; sx < 4; sx++) {
                int iy = y * 8 + sy * 2, ix = x * 8 + sx * 2;
                const float* p = in + ((size_t)iy * 512 + ix) * 3;
                const float* q = p + 512 * 3;
                float cx = 0.25f * (p[0] + p[3] + q[0] + q[3]);
                float cy = 0.25f * (p[1] + p[4] + q[1] + q[4]);
                float cz = 0.25f * (p[2] + p[5] + q[2] + q[5]);
                L1[(size_t)(y * 4 + sy) * 256 + (x * 4 + sx)] =
                    make_float4(cx, cy, cz, 0.0f);
                a2x[sy >> 1][sx >> 1] += cx;
                a2y[sy >> 1][sx >> 1] += cy;
                a2z[sy >> 1][sx >> 1] += cz;
            }
        }
        float a3x = 0.f, a3y = 0.f, a3z = 0.f;
        #pragma unroll
        for (int j = 0; j < 2; j++)
            #pragma unroll
            for (int i = 0; i < 2; i++) {
                float cx = 0.25f * a2x[j][i];
                float cy = 0.25f * a2y[j][i];
                float cz = 0.25f * a2z[j][i];
                L2[(size_t)(y * 2 + j) * 128 + (x * 2 + i)] =
                    make_float4(cx, cy, cz, 0.0f);
                a3x += cx; a3y += cy; a3z += cz;
            }
        L3[(size_t)y * 64 + x] =
            make_float4(0.25f * a3x, 0.25f * a3y, 0.25f * a3z, 0.0f);
    } else if (idx < 49152) {
        // ---- tex0: level-1 texel (64x64) ----
        int j = idx - 24576;
        int x = j & 63, y = (j >> 6) & 63, f = j >> 12;
        const float* in = t0 + (size_t)f * 128 * 128 * 3;
        const float* p = in + ((size_t)(2 * y) * 128 + 2 * x) * 3;
        const float* q = p + 128 * 3;
        g_p0[(size_t)f * 4096 + (size_t)y * 64 + x] = make_float4(
            0.25f * (p[0] + p[3] + q[0] + q[3]),
            0.25f * (p[1] + p[4] + q[1] + q[4]),
            0.25f * (p[2] + p[5] + q[2] + q[5]), 0.0f);
    }
}

// ---------------------------------------------------------------------------
// Build kernel 2: per-face in-smem reduction of the remaining levels.
// Blocks 0..5: tex1 faces (level3 -> 4..9). Blocks 6..11: tex0 (level1 -> 2..7).
// Dynamic smem: A buffer 64x64 float4 + B buffer 32x32 float4 = 81920 bytes.
// ---------------------------------------------------------------------------
__global__ void build2() {
    extern __shared__ float4 sm[];
    float4* A = sm;
    float4* Bb = sm + 4096;

    int b = blockIdx.x;
    float4* pyr;
    const int* offs;
    const float4* src;
    int lstart, lmax, f;
    if (b < 6) {
        f = b; pyr = g_p1; offs = OFF1;
        src = g_p1 + 491520 + (size_t)f * 4096;   // level 3, 64x64
        lstart = 4; lmax = 9;
    } else {
        f = b - 6; pyr = g_p0; offs = OFF0;
        src = g_p0 + 0 + (size_t)f * 4096;        // level 1, 64x64
        lstart = 2; lmax = 7;
    }
    for (int i = threadIdx.x; i < 4096; i += blockDim.x) A[i] = src[i];
    __syncthreads();

    int curR = 64;
    for (int l = lstart; l <= lmax; l++) {
        int R = curR >> 1;
        float4* dst_g = pyr + offs[l] + (size_t)f * R * R;
        for (int i = threadIdx.x; i < R * R; i += blockDim.x) {
            int x = i % R, y = i / R;
            const float4* p = A + (size_t)(2 * y) * curR + 2 * x;
            const float4* q = p + curR;
            float4 m = make_float4(
                0.25f * (p[0].x + p[1].x + q[0].x + q[1].x),
                0.25f * (p[0].y + p[1].y + q[0].y + q[1].y),
                0.25f * (p[0].z + p[1].z + q[0].z + q[1].z), 0.0f);
            Bb[i] = m;
            dst_g[i] = m;
        }
        __syncthreads();
        float4* tmp = A; A = Bb; Bb = tmp;
        curR = R;
    }
}

// ---------------------------------------------------------------------------
// Sampling
// ---------------------------------------------------------------------------
struct TapIdx { int i00, i01, i10, i11; float w00, w01, w10, w11; };

__device__ __forceinline__ TapIdx tap_idx(int R, float u, float v) {
    float x = u * (float)R - 0.5f;
    float y = v * (float)R - 0.5f;
    float x0f = floorf(x), y0f = floorf(y);
    float fx = x - x0f, fy = y - y0f;
    int xi = (int)x0f, yi = (int)y0f;
    int x0 = min(max(xi, 0), R - 1);
    int x1 = min(max(xi + 1, 0), R - 1);
    int y0 = min(max(yi, 0), R - 1);
    int y1 = min(max(yi + 1, 0), R - 1);
    TapIdx t;
    t.i00 = y0 * R + x0; t.i01 = y0 * R + x1;
    t.i10 = y1 * R + x0; t.i11 = y1 * R + x1;
    t.w00 = (1.0f - fx) * (1.0f - fy);
    t.w01 = fx * (1.0f - fy);
    t.w10 = (1.0f - fx) * fy;
    t.w11 = fx * fy;
    return t;
}

__device__ __forceinline__ float3 bil4(const float4* __restrict__ t, int R,
                                       int face, float u, float v) {
    TapIdx ti = tap_idx(R, u, v);
    const float4* b = t + (size_t)face * R * R;
    float4 g00 = __ldg(b + ti.i00);
    float4 g01 = __ldg(b + ti.i01);
    float4 g10 = __ldg(b + ti.i10);
    float4 g11 = __ldg(b + ti.i11);
    float3 r;
    r.x = ti.w00 * g00.x + ti.w01 * g01.x + ti.w10 * g10.x + ti.w11 * g11.x;
    r.y = ti.w00 * g00.y + ti.w01 * g01.y + ti.w10 * g10.y + ti.w11 * g11.y;
    r.z = ti.w00 * g00.z + ti.w01 * g01.z + ti.w10 * g10.z + ti.w11 * g11.z;
    return r;
}

// cold path: level 0 lives in the float3 input buffer
__device__ __forceinline__ float3 bil3(const float* __restrict__ t, int R,
                                       int face, float u, float v) {
    TapIdx ti = tap_idx(R, u, v);
    const float* b = t + (size_t)face * R * R * 3;
    const float* p00 = b + (size_t)ti.i00 * 3;
    const float* p01 = b + (size_t)ti.i01 * 3;
    const float* p10 = b + (size_t)ti.i10 * 3;
    const float* p11 = b + (size_t)ti.i11 * 3;
    float3 r;
    r.x = ti.w00 * p00[0] + ti.w01 * p01[0] + ti.w10 * p10[0] + ti.w11 * p11[0];
    r.y = ti.w00 * p00[1] + ti.w01 * p01[1] + ti.w10 * p10[1] + ti.w11 * p11[1];
    r.z = ti.w00 * p00[2] + ti.w01 * p01[2] + ti.w10 * p10[2] + ti.w11 * p11[2];
    return r;
}

__device__ __forceinline__ float3 sample_pyr(const float* __restrict__ base3,
                                             const float4* __restrict__ pyr,
                                             const int* offs, int baseR,
                                             int lmax, float m,
                                             int face, float u, float v) {
    m = fminf(m, (float)lmax);            // m >= 0 guaranteed by caller
    int l0 = (int)m;
    float f = m - (float)l0;
    float3 c;
    if (l0 == 0)
        c = bil3(base3, baseR, face, u, v);            // effectively never
    else
        c = bil4(pyr + offs[l0], baseR >> l0, face, u, v);
    if (f > 0.0f) {
        int l1 = l0 + 1;
        float3 c1 = bil4(pyr + offs[l1], baseR >> l1, face, u, v);
        float g = 1.0f - f;
        c.x = g * c.x + f * c1.x;
        c.y = g * c.y + f * c1.y;
        c.z = g * c.z + f * c1.z;
    }
    return c;
}

__global__ void sample_kernel(const float* __restrict__ vd,
                              const float* __restrict__ sa,
                              const float* __restrict__ nu,
                              const float* __restrict__ t0,
                              const float* __restrict__ t1,
                              const float* __restrict__ pbr,
                              const float* __restrict__ pmul,
                              const float* __restrict__ pmb,
                              float* __restrict__ out, int n) {
    int i = blockIdx.x * blockDim.x + threadIdx.x;
    if (i >= n) return;

    float vx = vd[3 * i + 0];
    float vy = vd[3 * i + 1];
    float vz = vd[3 * i + 2];
    float ax = fabsf(vx), ay = fabsf(vy), az = fabsf(vz);
    float ma = fmaxf(ax, fmaxf(ay, az));

    float saTexel = (1.0f / ma) * (1.0f / (512.0f * 512.0f));
    float mip = (sa[i] - logf(saTexel)) * 0.36067376022224085f   // 1/(2 ln 4)
                + pmb[0] + 0.5f * nu[i];
    mip = fmaxf(mip, 0.0f);

    int face; float sc, tc, den;
    bool is_x = (ax >= ay) && (ax >= az);
    bool is_y = (!is_x) && (ay >= az);
    if (is_x)      { face = (vx >= 0.0f) ? 0 : 1; den = ax; sc = (vx >= 0.0f) ? -vz :  vz; tc = -vy; }
    else if (is_y) { face = (vy >= 0.0f) ? 2 : 3; den = ay; sc =  vx;                      tc = (vy >= 0.0f) ?  vz : -vz; }
    else           { face = (vz >= 0.0f) ? 4 : 5; den = az; sc = (vz >= 0.0f) ?  vx : -vx; tc = -vy; }
    float inv = 1.0f / den;
    float u = 0.5f * (sc * inv + 1.0f);
    float v = 0.5f * (tc * inv + 1.0f);

    float3 s0 = sample_pyr(t0, g_p0, OFF0, 128, 7, mip, face, u, v);
    float3 s1 = sample_pyr(t1, g_p1, OFF1, 512, 9, mip, face, u, v);

    float br  = fminf(fmaxf(pbr[0], -1.0f), 2.0f);
    float mul = pmul[0];
    float ox = fminf(fmaxf(__expf(br + mul * (s0.x + s1.x)), 0.01f), 1000.0f);
    float oy = fminf(fmaxf(__expf(br + mul * (s0.y + s1.y)), 0.01f), 1000.0f);
    float oz = fminf(fmaxf(__expf(br + mul * (s0.z + s1.z)), 0.01f), 1000.0f);
    out[3 * i + 0] = ox;
    out[3 * i + 1] = oy;
    out[3 * i + 2] = oz;
}

extern "C" void kernel_launch(void* const* d_in, const int* in_sizes, int n_in,
                              void* d_out, int out_size) {
    const float* vd  = (const float*)d_in[0];  // viewdirs  [B,3]
    const float* sa  = (const float*)d_in[1];  // saSample  [B]
    const float* nu  = (const float*)d_in[2];  // noise_u   [B]
    const float* t0  = (const float*)d_in[3];  // bg_mat0   [1,6,128,128,3]
    const float* t1  = (const float*)d_in[4];  // bg_mat1   [1,6,512,512,3]
    const float* br  = (const float*)d_in[5];  // brightness scalar
    const float* mul = (const float*)d_in[6];  // mul scalar
    const float* mb  = (const float*)d_in[7];  // mipbias scalar
    int n = in_sizes[1];

    cudaFuncSetAttribute(build2, cudaFuncAttributeMaxDynamicSharedMemorySize,
                         81920);

    build1<<<192, 256>>>(t0, t1);              // tex1 L1-3 + tex0 L1
    build2<<<12, 256, 81920>>>();              // all remaining levels, per-face
    sample_kernel<<<(n + 255) / 256, 256>>>(vd, sa, nu, t0, t1, br, mul, mb,
                                            (float*)d_out, n);
}

// round 3
// speedup vs baseline: 1.5147x; 1.0507x over previous
#include <cuda_runtime.h>
#include <math.h>

// ---------------------------------------------------------------------------
// Pyramid scratch (float4-padded texels; w unused). Level 0 stays in the
// float3 input buffers (cold path: mip >= ~3.5 in practice).
// ---------------------------------------------------------------------------
__device__ float4 g_p0[32766];    // tex0 levels 1..7  (R=64..1)
__device__ float4 g_p1[524286];   // tex1 levels 1..9  (R=256..1)

// offsets of level l (float4 units); index 0 unused
__constant__ int OFF0[8]  = {0, 0, 24576, 30720, 32256, 32640, 32736, 32760};
__constant__ int OFF1[10] = {0, 0, 393216, 491520, 516096, 522240,
                             523776, 524160, 524256, 524280};

// ---------------------------------------------------------------------------
// buildA: levels 1..3 of both pyramids, block-tiled, coalesced float4 loads.
// Each block covers a 32x32 L1 tile (64x64 input texels). Thread t computes
// 4 adjacent L1 texels from 12 aligned LDG.128, L2/L3 reduced in smem.
// Grid: 384 blocks for tex1 (6 faces x 8x8 tiles) + 24 for tex0 (6 x 2x2).
// ---------------------------------------------------------------------------
__device__ __forceinline__ void build_tile(
    const float* __restrict__ in, int inRowF,   // input (float3), floats/row
    float4* __restrict__ L1, int R1,            // face-local level-1 ptr
    float4* __restrict__ L2,                    // face-local level-2 ptr
    float4* __restrict__ L3,                    // face-local level-3 ptr
    int bx, int by, int tid,
    float4* s1, float4* s2)
{
    int lx4 = (tid & 7) * 4;          // first of 4 L1 texels in x (0..28)
    int ly  = tid >> 3;               // L1 y within tile (0..31)
    int X0 = bx * 32 + lx4;
    int Y  = by * 32 + ly;

    const float* r0 = in + (size_t)(2 * Y) * inRowF + 6 * X0;  // 16B aligned
    const float* r1 = r0 + inRowF;
    float a[24], b[24];
    #pragma unroll
    for (int q = 0; q < 6; q++) {
        *(float4*)(a + 4 * q) = __ldg((const float4*)r0 + q);
        *(float4*)(b + 4 * q) = __ldg((const float4*)r1 + q);
    }
    #pragma unroll
    for (int k = 0; k < 4; k++) {
        float cx = 0.25f * (a[6*k+0] + a[6*k+3] + b[6*k+0] + b[6*k+3]);
        float cy = 0.25f * (a[6*k+1] + a[6*k+4] + b[6*k+1] + b[6*k+4]);
        float cz = 0.25f * (a[6*k+2] + a[6*k+5] + b[6*k+2] + b[6*k+5]);
        float4 t = make_float4(cx, cy, cz, 0.0f);
        s1[ly * 32 + lx4 + k] = t;
        L1[(size_t)Y * R1 + X0 + k] = t;
    }
    __syncthreads();

    // L2: 16x16 per tile, one texel per thread
    {
        int x2 = tid & 15, y2 = tid >> 4;
        float4 p00 = s1[(2*y2) * 32 + 2*x2];
        float4 p01 = s1[(2*y2) * 32 + 2*x2 + 1];
        float4 p10 = s1[(2*y2+1) * 32 + 2*x2];
        float4 p11 = s1[(2*y2+1) * 32 + 2*x2 + 1];
        float4 m = make_float4(0.25f * (p00.x + p01.x + p10.x + p11.x),
                               0.25f * (p00.y + p01.y + p10.y + p11.y),
                               0.25f * (p00.z + p01.z + p10.z + p11.z), 0.0f);
        s2[y2 * 16 + x2] = m;
        int R2 = R1 >> 1;
        L2[(size_t)(by * 16 + y2) * R2 + bx * 16 + x2] = m;
    }
    __syncthreads();

    // L3: 8x8 per tile
    if (tid < 64) {
        int x3 = tid & 7, y3 = tid >> 3;
        float4 p00 = s2[(2*y3) * 16 + 2*x3];
        float4 p01 = s2[(2*y3) * 16 + 2*x3 + 1];
        float4 p10 = s2[(2*y3+1) * 16 + 2*x3];
        float4 p11 = s2[(2*y3+1) * 16 + 2*x3 + 1];
        float4 m = make_float4(0.25f * (p00.x + p01.x + p10.x + p11.x),
                               0.25f * (p00.y + p01.y + p10.y + p11.y),
                               0.25f * (p00.z + p01.z + p10.z + p11.z), 0.0f);
        int R3 = R1 >> 2;
        L3[(size_t)(by * 8 + y3) * R3 + bx * 8 + x3] = m;
    }
}

__global__ void buildA(const float* __restrict__ t0,
                       const float* __restrict__ t1) {
    __shared__ float4 s1[32 * 32];
    __shared__ float4 s2[16 * 16];
    int b = blockIdx.x, tid = threadIdx.x;
    if (b < 384) {                       // tex1: 6 faces x 64 tiles
        int f = b >> 6, q = b & 63;
        int bx = q & 7, by = q >> 3;
        build_tile(t1 + (size_t)f * 512 * 512 * 3, 1536,
                   g_p1 + OFF1[1] + (size_t)f * 256 * 256, 256,
                   g_p1 + OFF1[2] + (size_t)f * 128 * 128,
                   g_p1 + OFF1[3] + (size_t)f * 64 * 64,
                   bx, by, tid, s1, s2);
    } else {                             // tex0: 6 faces x 4 tiles
        int j = b - 384;
        int f = j >> 2, q = j & 3;
        int bx = q & 1, by = q >> 1;
        build_tile(t0 + (size_t)f * 128 * 128 * 3, 384,
                   g_p0 + OFF0[1] + (size_t)f * 64 * 64, 64,
                   g_p0 + OFF0[2] + (size_t)f * 32 * 32,
                   g_p0 + OFF0[3] + (size_t)f * 16 * 16,
                   bx, by, tid, s1, s2);
    }
}

// ---------------------------------------------------------------------------
// buildTail: per-face in-smem reduction of remaining levels (from L3 up).
// Blocks 0..5: tex1 faces (64x64 L3 -> levels 4..9).
// Blocks 6..11: tex0 faces (16x16 L3 -> levels 4..7).
// ---------------------------------------------------------------------------
__global__ void buildTail() {
    extern __shared__ float4 sm[];
    float4* A = sm;
    float4* Bb = sm + 4096;

    int b = blockIdx.x;
    float4* pyr; const int* offs; int Rsrc, lmax, f;
    if (b < 6) { f = b;     pyr = g_p1; offs = OFF1; Rsrc = 64; lmax = 9; }
    else       { f = b - 6; pyr = g_p0; offs = OFF0; Rsrc = 16; lmax = 7; }

    const float4* src = pyr + offs[3] + (size_t)f * Rsrc * Rsrc;
    for (int i = threadIdx.x; i < Rsrc * Rsrc; i += blockDim.x) A[i] = src[i];
    __syncthreads();

    int curR = Rsrc;
    for (int l = 4; l <= lmax; l++) {
        int R = curR >> 1;
        float4* dst_g = pyr + offs[l] + (size_t)f * R * R;
        for (int i = threadIdx.x; i < R * R; i += blockDim.x) {
            int x = i % R, y = i / R;
            const float4* p = A + (size_t)(2 * y) * curR + 2 * x;
            const float4* q = p + curR;
            float4 m = make_float4(
                0.25f * (p[0].x + p[1].x + q[0].x + q[1].x),
                0.25f * (p[0].y + p[1].y + q[0].y + q[1].y),
                0.25f * (p[0].z + p[1].z + q[0].z + q[1].z), 0.0f);
            Bb[i] = m;
            dst_g[i] = m;
        }
        __syncthreads();
        float4* tmp = A; A = Bb; Bb = tmp;
        curR = R;
    }
}

// ---------------------------------------------------------------------------
// Sampling
// ---------------------------------------------------------------------------
struct TapIdx { int i00, i01, i10, i11; float w00, w01, w10, w11; };

__device__ __forceinline__ TapIdx tap_idx(int R, float u, float v) {
    float x = u * (float)R - 0.5f;
    float y = v * (float)R - 0.5f;
    float x0f = floorf(x), y0f = floorf(y);
    float fx = x - x0f, fy = y - y0f;
    int xi = (int)x0f, yi = (int)y0f;
    int x0 = min(max(xi, 0), R - 1);
    int x1 = min(max(xi + 1, 0), R - 1);
    int y0 = min(max(yi, 0), R - 1);
    int y1 = min(max(yi + 1, 0), R - 1);
    TapIdx t;
    t.i00 = y0 * R + x0; t.i01 = y0 * R + x1;
    t.i10 = y1 * R + x0; t.i11 = y1 * R + x1;
    t.w00 = (1.0f - fx) * (1.0f - fy);
    t.w01 = fx * (1.0f - fy);
    t.w10 = (1.0f - fx) * fy;
    t.w11 = fx * fy;
    return t;
}

__device__ __forceinline__ float3 bil4(const float4* __restrict__ t, int R,
                                       int face, float u, float v) {
    TapIdx ti = tap_idx(R, u, v);
    const float4* b = t + (size_t)face * R * R;
    float4 g00 = __ldg(b + ti.i00);
    float4 g01 = __ldg(b + ti.i01);
    float4 g10 = __ldg(b + ti.i10);
    float4 g11 = __ldg(b + ti.i11);
    float3 r;
    r.x = ti.w00 * g00.x + ti.w01 * g01.x + ti.w10 * g10.x + ti.w11 * g11.x;
    r.y = ti.w00 * g00.y + ti.w01 * g01.y + ti.w10 * g10.y + ti.w11 * g11.y;
    r.z = ti.w00 * g00.z + ti.w01 * g01.z + ti.w10 * g10.z + ti.w11 * g11.z;
    return r;
}

// cold path: level 0 lives in the float3 input buffer
__device__ __forceinline__ float3 bil3(const float* __restrict__ t, int R,
                                       int face, float u, float v) {
    TapIdx ti = tap_idx(R, u, v);
    const float* b = t + (size_t)face * R * R * 3;
    const float* p00 = b + (size_t)ti.i00 * 3;
    const float* p01 = b + (size_t)ti.i01 * 3;
    const float* p10 = b + (size_t)ti.i10 * 3;
    const float* p11 = b + (size_t)ti.i11 * 3;
    float3 r;
    r.x = ti.w00 * p00[0] + ti.w01 * p01[0] + ti.w10 * p10[0] + ti.w11 * p11[0];
    r.y = ti.w00 * p00[1] + ti.w01 * p01[1] + ti.w10 * p10[1] + ti.w11 * p11[1];
    r.z = ti.w00 * p00[2] + ti.w01 * p01[2] + ti.w10 * p10[2] + ti.w11 * p11[2];
    return r;
}

__device__ __forceinline__ float3 sample_pyr(const float* __restrict__ base3,
                                             const float4* __restrict__ pyr,
                                             const int* offs, int baseR,
                                             int lmax, float m,
                                             int face, float u, float v) {
    m = fminf(m, (float)lmax);            // m >= 0 guaranteed by caller
    int l0 = (int)m;
    float f = m - (float)l0;
    float3 c;
    if (l0 == 0)
        c = bil3(base3, baseR, face, u, v);            // effectively never
    else
        c = bil4(pyr + offs[l0], baseR >> l0, face, u, v);
    if (f > 0.0f) {
        int l1 = l0 + 1;
        float3 c1 = bil4(pyr + offs[l1], baseR >> l1, face, u, v);
        float g = 1.0f - f;
        c.x = g * c.x + f * c1.x;
        c.y = g * c.y + f * c1.y;
        c.z = g * c.z + f * c1.z;
    }
    return c;
}

__global__ void sample_kernel(const float* __restrict__ vd,
                              const float* __restrict__ sa,
                              const float* __restrict__ nu,
                              const float* __restrict__ t0,
                              const float* __restrict__ t1,
                              const float* __restrict__ pbr,
                              const float* __restrict__ pmul,
                              const float* __restrict__ pmb,
                              float* __restrict__ out, int n) {
    int i = blockIdx.x * blockDim.x + threadIdx.x;
    if (i >= n) return;

    float vx = vd[3 * i + 0];
    float vy = vd[3 * i + 1];
    float vz = vd[3 * i + 2];
    float ax = fabsf(vx), ay = fabsf(vy), az = fabsf(vz);
    float ma = fmaxf(ax, fmaxf(ay, az));

    // log(saTexel) = -(log(ma) + 18*ln2);  1/(2 ln 4) = 0.36067376
    float mip = (sa[i] + __logf(ma) + 12.476649250079015f)
                * 0.36067376022224085f + pmb[0] + 0.5f * nu[i];
    mip = fmaxf(mip, 0.0f);

    int face; float sc, tc, den;
    bool is_x = (ax >= ay) && (ax >= az);
    bool is_y = (!is_x) && (ay >= az);
    if (is_x)      { face = (vx >= 0.0f) ? 0 : 1; den = ax; sc = (vx >= 0.0f) ? -vz :  vz; tc = -vy; }
    else if (is_y) { face = (vy >= 0.0f) ? 2 : 3; den = ay; sc =  vx;                      tc = (vy >= 0.0f) ?  vz : -vz; }
    else           { face = (vz >= 0.0f) ? 4 : 5; den = az; sc = (vz >= 0.0f) ?  vx : -vx; tc = -vy; }
    float inv = __fdividef(1.0f, den);
    float u = 0.5f * (sc * inv + 1.0f);
    float v = 0.5f * (tc * inv + 1.0f);

    float3 s0 = sample_pyr(t0, g_p0, OFF0, 128, 7, mip, face, u, v);
    float3 s1 = sample_pyr(t1, g_p1, OFF1, 512, 9, mip, face, u, v);

    float br  = fminf(fmaxf(pbr[0], -1.0f), 2.0f);
    float mul = pmul[0];
    float ox = fminf(fmaxf(__expf(br + mul * (s0.x + s1.x)), 0.01f), 1000.0f);
    float oy = fminf(fmaxf(__expf(br + mul * (s0.y + s1.y)), 0.01f), 1000.0f);
    float oz = fminf(fmaxf(__expf(br + mul * (s0.z + s1.z)), 0.01f), 1000.0f);
    out[3 * i + 0] = ox;
    out[3 * i + 1] = oy;
    out[3 * i + 2] = oz;
}

extern "C" void kernel_launch(void* const* d_in, const int* in_sizes, int n_in,
                              void* d_out, int out_size) {
    const float* vd  = (const float*)d_in[0];  // viewdirs  [B,3]
    const float* sa  = (const float*)d_in[1];  // saSample  [B]
    const float* nu  = (const float*)d_in[2];  // noise_u   [B]
    const float* t0  = (const float*)d_in[3];  // bg_mat0   [1,6,128,128,3]
    const float* t1  = (const float*)d_in[4];  // bg_mat1   [1,6,512,512,3]
    const float* br  = (const float*)d_in[5];  // brightness scalar
    const float* mul = (const float*)d_in[6];  // mul scalar
    const float* mb  = (const float*)d_in[7];  // mipbias scalar
    int n = in_sizes[1];

    cudaFuncSetAttribute(buildTail, cudaFuncAttributeMaxDynamicSharedMemorySize,
                         81920);

    buildA<<<408, 256>>>(t0, t1);              // L1-3 of both pyramids
    buildTail<<<12, 256, 81920>>>();           // L4+ per face
    sample_kernel<<<(n + 255) / 256, 256>>>(vd, sa, nu, t0, t1, br, mul, mb,
                                            (float*)d_out, n);
}

// round 4
// speedup vs baseline: 1.5821x; 1.0445x over previous
#include <cuda_runtime.h>
#include <math.h>

// ---------------------------------------------------------------------------
// Pyramid scratch (float4-padded texels; w unused). Level 0 stays in the
// float3 input buffers (cold path: mip >= ~3.5 in practice).
// ---------------------------------------------------------------------------
__device__ float4 g_p0[32766];    // tex0 levels 1..7  (R=64..1)
__device__ float4 g_p1[524286];   // tex1 levels 1..9  (R=256..1)

// offsets of level l (float4 units); index 0 unused
__constant__ int OFF0[8]  = {0, 0, 24576, 30720, 32256, 32640, 32736, 32760};
__constant__ int OFF1[10] = {0, 0, 393216, 491520, 516096, 522240,
                             523776, 524160, 524256, 524280};

// ---------------------------------------------------------------------------
// buildA: levels 1..3 of both pyramids. 512 threads/block, each thread makes
// 2 adjacent L1 texels from 6 aligned LDG.128; L2/L3 reduced in smem.
// Block = one 32x32 L1 tile (64x64 input). 384 tex1 blocks + 24 tex0 blocks.
// ---------------------------------------------------------------------------
__device__ __forceinline__ void build_tile(
    const float* __restrict__ in, int inRowF,   // input (float3), floats/row
    float4* __restrict__ L1, int R1,            // face-local level-1 ptr
    float4* __restrict__ L2,                    // face-local level-2 ptr
    float4* __restrict__ L3,                    // face-local level-3 ptr
    int bx, int by, int tid,
    float4* s1, float4* s2)
{
    int lx2 = (tid & 15) * 2;         // first of 2 L1 texels in x (0..30)
    int ly  = tid >> 4;               // L1 y within tile (0..31)
    int X0 = bx * 32 + lx2;
    int Y  = by * 32 + ly;

    const float* r0 = in + (size_t)(2 * Y) * inRowF + 6 * X0;  // 16B aligned
    const float* r1 = r0 + inRowF;
    float a[12], b[12];
    #pragma unroll
    for (int q = 0; q < 3; q++) {
        *(float4*)(a + 4 * q) = __ldg((const float4*)r0 + q);
        *(float4*)(b + 4 * q) = __ldg((const float4*)r1 + q);
    }
    #pragma unroll
    for (int k = 0; k < 2; k++) {
        float cx = 0.25f * (a[6*k+0] + a[6*k+3] + b[6*k+0] + b[6*k+3]);
        float cy = 0.25f * (a[6*k+1] + a[6*k+4] + b[6*k+1] + b[6*k+4]);
        float cz = 0.25f * (a[6*k+2] + a[6*k+5] + b[6*k+2] + b[6*k+5]);
        float4 t = make_float4(cx, cy, cz, 0.0f);
        s1[ly * 32 + lx2 + k] = t;
        L1[(size_t)Y * R1 + X0 + k] = t;
    }
    __syncthreads();

    // L2: 16x16 per tile
    if (tid < 256) {
        int x2 = tid & 15, y2 = tid >> 4;
        float4 p00 = s1[(2*y2) * 32 + 2*x2];
        float4 p01 = s1[(2*y2) * 32 + 2*x2 + 1];
        float4 p10 = s1[(2*y2+1) * 32 + 2*x2];
        float4 p11 = s1[(2*y2+1) * 32 + 2*x2 + 1];
        float4 m = make_float4(0.25f * (p00.x + p01.x + p10.x + p11.x),
                               0.25f * (p00.y + p01.y + p10.y + p11.y),
                               0.25f * (p00.z + p01.z + p10.z + p11.z), 0.0f);
        s2[y2 * 16 + x2] = m;
        int R2 = R1 >> 1;
        L2[(size_t)(by * 16 + y2) * R2 + bx * 16 + x2] = m;
    }
    __syncthreads();

    // L3: 8x8 per tile
    if (tid < 64) {
        int x3 = tid & 7, y3 = tid >> 3;
        float4 p00 = s2[(2*y3) * 16 + 2*x3];
        float4 p01 = s2[(2*y3) * 16 + 2*x3 + 1];
        float4 p10 = s2[(2*y3+1) * 16 + 2*x3];
        float4 p11 = s2[(2*y3+1) * 16 + 2*x3 + 1];
        float4 m = make_float4(0.25f * (p00.x + p01.x + p10.x + p11.x),
                               0.25f * (p00.y + p01.y + p10.y + p11.y),
                               0.25f * (p00.z + p01.z + p10.z + p11.z), 0.0f);
        int R3 = R1 >> 2;
        L3[(size_t)(by * 8 + y3) * R3 + bx * 8 + x3] = m;
    }
}

__global__ void buildA(const float* __restrict__ t0,
                       const float* __restrict__ t1) {
    __shared__ float4 s1[32 * 32];
    __shared__ float4 s2[16 * 16];
    int b = blockIdx.x, tid = threadIdx.x;
    if (b < 384) {                       // tex1: 6 faces x 64 tiles
        int f = b >> 6, q = b & 63;
        int bx = q & 7, by = q >> 3;
        build_tile(t1 + (size_t)f * 512 * 512 * 3, 1536,
                   g_p1 + OFF1[1] + (size_t)f * 256 * 256, 256,
                   g_p1 + OFF1[2] + (size_t)f * 128 * 128,
                   g_p1 + OFF1[3] + (size_t)f * 64 * 64,
                   bx, by, tid, s1, s2);
    } else {                             // tex0: 6 faces x 4 tiles
        int j = b - 384;
        int f = j >> 2, q = j & 3;
        int bx = q & 1, by = q >> 1;
        build_tile(t0 + (size_t)f * 128 * 128 * 3, 384,
                   g_p0 + OFF0[1] + (size_t)f * 64 * 64, 64,
                   g_p0 + OFF0[2] + (size_t)f * 32 * 32,
                   g_p0 + OFF0[3] + (size_t)f * 16 * 16,
                   bx, by, tid, s1, s2);
    }
}

// ---------------------------------------------------------------------------
// buildTail: per-face in-smem reduction of remaining levels (from L3 up).
// ---------------------------------------------------------------------------
__global__ void buildTail() {
    extern __shared__ float4 sm[];
    float4* A = sm;
    float4* Bb = sm + 4096;

    int b = blockIdx.x;
    float4* pyr; const int* offs; int Rsrc, lmax, f;
    if (b < 6) { f = b;     pyr = g_p1; offs = OFF1; Rsrc = 64; lmax = 9; }
    else       { f = b - 6; pyr = g_p0; offs = OFF0; Rsrc = 16; lmax = 7; }

    const float4* src = pyr + offs[3] + (size_t)f * Rsrc * Rsrc;
    for (int i = threadIdx.x; i < Rsrc * Rsrc; i += blockDim.x) A[i] = src[i];
    __syncthreads();

    int curR = Rsrc;
    for (int l = 4; l <= lmax; l++) {
        int R = curR >> 1;
        float4* dst_g = pyr + offs[l] + (size_t)f * R * R;
        for (int i = threadIdx.x; i < R * R; i += blockDim.x) {
            int x = i % R, y = i / R;
            const float4* p = A + (size_t)(2 * y) * curR + 2 * x;
            const float4* q = p + curR;
            float4 m = make_float4(
                0.25f * (p[0].x + p[1].x + q[0].x + q[1].x),
                0.25f * (p[0].y + p[1].y + q[0].y + q[1].y),
                0.25f * (p[0].z + p[1].z + q[0].z + q[1].z), 0.0f);
            Bb[i] = m;
            dst_g[i] = m;
        }
        __syncthreads();
        float4* tmp = A; A = Bb; Bb = tmp;
        curR = R;
    }
}

// ---------------------------------------------------------------------------
// Sampling
// ---------------------------------------------------------------------------
struct TapIdx { int i00, i01, i10, i11; float w00, w01, w10, w11; };

__device__ __forceinline__ TapIdx tap_idx(int R, float u, float v) {
    float x = u * (float)R - 0.5f;
    float y = v * (float)R - 0.5f;
    float x0f = floorf(x), y0f = floorf(y);
    float fx = x - x0f, fy = y - y0f;
    int xi = (int)x0f, yi = (int)y0f;
    int x0 = min(max(xi, 0), R - 1);
    int x1 = min(max(xi + 1, 0), R - 1);
    int y0 = min(max(yi, 0), R - 1);
    int y1 = min(max(yi + 1, 0), R - 1);
    TapIdx t;
    t.i00 = y0 * R + x0; t.i01 = y0 * R + x1;
    t.i10 = y1 * R + x0; t.i11 = y1 * R + x1;
    t.w00 = (1.0f - fx) * (1.0f - fy);
    t.w01 = fx * (1.0f - fy);
    t.w10 = (1.0f - fx) * fy;
    t.w11 = fx * fy;
    return t;
}

__device__ __forceinline__ float3 bil4(const float4* __restrict__ t, int R,
                                       int face, float u, float v) {
    TapIdx ti = tap_idx(R, u, v);
    const float4* b = t + (size_t)face * R * R;
    float4 g00 = __ldg(b + ti.i00);
    float4 g01 = __ldg(b + ti.i01);
    float4 g10 = __ldg(b + ti.i10);
    float4 g11 = __ldg(b + ti.i11);
    float3 r;
    r.x = ti.w00 * g00.x + ti.w01 * g01.x + ti.w10 * g10.x + ti.w11 * g11.x;
    r.y = ti.w00 * g00.y + ti.w01 * g01.y + ti.w10 * g10.y + ti.w11 * g11.y;
    r.z = ti.w00 * g00.z + ti.w01 * g01.z + ti.w10 * g10.z + ti.w11 * g11.z;
    return r;
}

// cold path: level 0 lives in the float3 input buffer
__device__ __forceinline__ float3 bil3(const float* __restrict__ t, int R,
                                       int face, float u, float v) {
    TapIdx ti = tap_idx(R, u, v);
    const float* b = t + (size_t)face * R * R * 3;
    const float* p00 = b + (size_t)ti.i00 * 3;
    const float* p01 = b + (size_t)ti.i01 * 3;
    const float* p10 = b + (size_t)ti.i10 * 3;
    const float* p11 = b + (size_t)ti.i11 * 3;
    float3 r;
    r.x = ti.w00 * p00[0] + ti.w01 * p01[0] + ti.w10 * p10[0] + ti.w11 * p11[0];
    r.y = ti.w00 * p00[1] + ti.w01 * p01[1] + ti.w10 * p10[1] + ti.w11 * p11[1];
    r.z = ti.w00 * p00[2] + ti.w01 * p01[2] + ti.w10 * p10[2] + ti.w11 * p11[2];
    return r;
}

__device__ __forceinline__ float3 sample_pyr(const float* __restrict__ base3,
                                             const float4* __restrict__ pyr,
                                             const int* offs, int baseR,
                                             int lmax, float m,
                                             int face, float u, float v) {
    m = fminf(m, (float)lmax);            // m >= 0 guaranteed by caller
    int l0 = (int)m;
    float f = m - (float)l0;
    float3 c;
    if (l0 == 0)
        c = bil3(base3, baseR, face, u, v);            // effectively never
    else
        c = bil4(pyr + offs[l0], baseR >> l0, face, u, v);
    if (f > 0.0f) {
        int l1 = l0 + 1;
        float3 c1 = bil4(pyr + offs[l1], baseR >> l1, face, u, v);
        float g = 1.0f - f;
        c.x = g * c.x + f * c1.x;
        c.y = g * c.y + f * c1.y;
        c.z = g * c.z + f * c1.z;
    }
    return c;
}

__global__ void __launch_bounds__(256) sample_kernel(
                              const float* __restrict__ vd,
                              const float* __restrict__ sa,
                              const float* __restrict__ nu,
                              const float* __restrict__ t0,
                              const float* __restrict__ t1,
                              const float* __restrict__ pbr,
                              const float* __restrict__ pmul,
                              const float* __restrict__ pmb,
                              float* __restrict__ out, int n) {
    __shared__ float s_io[768];           // 256 rays x 3 floats
    int tid = threadIdx.x;
    int base = blockIdx.x * 256;
    int i = base + tid;
    bool full = (base + 256 <= n);

    float vx, vy, vz;
    if (full) {
        if (tid < 192)
            ((float4*)s_io)[tid] =
                __ldg((const float4*)(vd + (size_t)base * 3) + tid);
        __syncthreads();
        vx = s_io[3 * tid + 0];
        vy = s_io[3 * tid + 1];
        vz = s_io[3 * tid + 2];
    } else {
        if (i >= n) return;
        vx = vd[3 * (size_t)i + 0];
        vy = vd[3 * (size_t)i + 1];
        vz = vd[3 * (size_t)i + 2];
    }

    float ax = fabsf(vx), ay = fabsf(vy), az = fabsf(vz);
    float ma = fmaxf(ax, fmaxf(ay, az));

    // log(saTexel) = -(log(ma) + 18*ln2);  1/(2 ln 4) = 0.36067376
    float mip = (sa[i] + __logf(ma) + 12.476649250079015f)
                * 0.36067376022224085f + pmb[0] + 0.5f * nu[i];
    mip = fmaxf(mip, 0.0f);

    int face; float sc, tc, den;
    bool is_x = (ax >= ay) && (ax >= az);
    bool is_y = (!is_x) && (ay >= az);
    if (is_x)      { face = (vx >= 0.0f) ? 0 : 1; den = ax; sc = (vx >= 0.0f) ? -vz :  vz; tc = -vy; }
    else if (is_y) { face = (vy >= 0.0f) ? 2 : 3; den = ay; sc =  vx;                      tc = (vy >= 0.0f) ?  vz : -vz; }
    else           { face = (vz >= 0.0f) ? 4 : 5; den = az; sc = (vz >= 0.0f) ?  vx : -vx; tc = -vy; }
    float inv = __fdividef(1.0f, den);
    float u = 0.5f * (sc * inv + 1.0f);
    float v = 0.5f * (tc * inv + 1.0f);

    float3 s0 = sample_pyr(t0, g_p0, OFF0, 128, 7, mip, face, u, v);
    float3 s1 = sample_pyr(t1, g_p1, OFF1, 512, 9, mip, face, u, v);

    float br  = fminf(fmaxf(pbr[0], -1.0f), 2.0f);
    float mul = pmul[0];
    float ox = fminf(fmaxf(__expf(br + mul * (s0.x + s1.x)), 0.01f), 1000.0f);
    float oy = fminf(fmaxf(__expf(br + mul * (s0.y + s1.y)), 0.01f), 1000.0f);
    float oz = fminf(fmaxf(__expf(br + mul * (s0.z + s1.z)), 0.01f), 1000.0f);

    if (full) {
        __syncthreads();                 // all vd reads from s_io done
        s_io[3 * tid + 0] = ox;
        s_io[3 * tid + 1] = oy;
        s_io[3 * tid + 2] = oz;
        __syncthreads();
        if (tid < 192)
            ((float4*)(out + (size_t)base * 3))[tid] = ((float4*)s_io)[tid];
    } else {
        out[3 * (size_t)i + 0] = ox;
        out[3 * (size_t)i + 1] = oy;
        out[3 * (size_t)i + 2] = oz;
    }
}

extern "C" void kernel_launch(void* const* d_in, const int* in_sizes, int n_in,
                              void* d_out, int out_size) {
    const float* vd  = (const float*)d_in[0];  // viewdirs  [B,3]
    const float* sa  = (const float*)d_in[1];  // saSample  [B]
    const float* nu  = (const float*)d_in[2];  // noise_u   [B]
    const float* t0  = (const float*)d_in[3];  // bg_mat0   [1,6,128,128,3]
    const float* t1  = (const float*)d_in[4];  // bg_mat1   [1,6,512,512,3]
    const float* br  = (const float*)d_in[5];  // brightness scalar
    const float* mul = (const float*)d_in[6];  // mul scalar
    const float* mb  = (const float*)d_in[7];  // mipbias scalar
    int n = in_sizes[1];

    cudaFuncSetAttribute(buildTail, cudaFuncAttributeMaxDynamicSharedMemorySize,
                         81920);

    buildA<<<408, 512>>>(t0, t1);              // L1-3 of both pyramids
    buildTail<<<12, 256, 81920>>>();           // L4+ per face
    sample_kernel<<<(n + 255) / 256, 256>>>(vd, sa, nu, t0, t1, br, mul, mb,
                                            (float*)d_out, n);
}

// round 5
// speedup vs baseline: 2.0107x; 1.2710x over previous
#include <cuda_runtime.h>
#include <cuda_fp16.h>
#include <math.h>

// ---------------------------------------------------------------------------
// Pyramid scratch (float4-padded texels; w unused). Level 0 stays in the
// float3 input buffers (cold path: mip >= ~3.5 in practice).
// ---------------------------------------------------------------------------
__device__ float4 g_p0[32766];    // tex0 levels 1..7  (R=64..1)
__device__ float4 g_p1[524286];   // tex1 levels 1..9  (R=256..1)

// offsets of level l (float4 units); index 0 unused
__constant__ int OFF0[8]  = {0, 0, 24576, 30720, 32256, 32640, 32736, 32760};
__constant__ int OFF1[10] = {0, 0, 393216, 491520, 516096, 522240,
                             523776, 524160, 524256, 524280};

// smem offsets (uint2/half4 units) of hot levels inside the sample kernel
// tex1 levels 4..9 at 0; tex0 levels 3..7 at 8192
__constant__ int SM1OFF[10] = {0, 0, 0, 0, 0, 6144, 7680, 8064, 8160, 8184};
__constant__ int SM0OFF[8]  = {0, 0, 0, 8192, 9728, 10112, 10208, 10232};

// ---------------------------------------------------------------------------
// buildA: levels 1..3 of both pyramids. 256 threads/block, 32x16 L1 tiles.
// Each thread makes 2 adjacent L1 texels from 6 aligned LDG.128.
// Grid: 768 tex1 blocks (6 faces x 8x16 tiles) + 48 tex0 (6 x 2x4).
// ---------------------------------------------------------------------------
__device__ __forceinline__ void build_tile(
    const float* __restrict__ in, int inRowF,   // input (float3), floats/row
    float4* __restrict__ L1, int R1,            // face-local level-1 ptr
    float4* __restrict__ L2,                    // face-local level-2 ptr
    float4* __restrict__ L3,                    // face-local level-3 ptr
    int bx, int by, int tid,
    float4* s1, float4* s2)
{
    int lx2 = (tid & 15) * 2;         // first of 2 L1 texels in x (0..30)
    int ly  = tid >> 4;               // L1 y within tile (0..15)
    int X0 = bx * 32 + lx2;
    int Y  = by * 16 + ly;

    const float* r0 = in + (size_t)(2 * Y) * inRowF + 6 * X0;  // 16B aligned
    const float* r1 = r0 + inRowF;
    float a[12], b[12];
    #pragma unroll
    for (int q = 0; q < 3; q++) {
        *(float4*)(a + 4 * q) = __ldg((const float4*)r0 + q);
        *(float4*)(b + 4 * q) = __ldg((const float4*)r1 + q);
    }
    #pragma unroll
    for (int k = 0; k < 2; k++) {
        float cx = 0.25f * (a[6*k+0] + a[6*k+3] + b[6*k+0] + b[6*k+3]);
        float cy = 0.25f * (a[6*k+1] + a[6*k+4] + b[6*k+1] + b[6*k+4]);
        float cz = 0.25f * (a[6*k+2] + a[6*k+5] + b[6*k+2] + b[6*k+5]);
        float4 t = make_float4(cx, cy, cz, 0.0f);
        s1[ly * 32 + lx2 + k] = t;
        L1[(size_t)Y * R1 + X0 + k] = t;
    }
    __syncthreads();

    // L2: 16x8 per tile
    if (tid < 128) {
        int x2 = tid & 15, y2 = tid >> 4;        // 0..7
        float4 p00 = s1[(2*y2) * 32 + 2*x2];
        float4 p01 = s1[(2*y2) * 32 + 2*x2 + 1];
        float4 p10 = s1[(2*y2+1) * 32 + 2*x2];
        float4 p11 = s1[(2*y2+1) * 32 + 2*x2 + 1];
        float4 m = make_float4(0.25f * (p00.x + p01.x + p10.x + p11.x),
                               0.25f * (p00.y + p01.y + p10.y + p11.y),
                               0.25f * (p00.z + p01.z + p10.z + p11.z), 0.0f);
        s2[y2 * 16 + x2] = m;
        int R2 = R1 >> 1;
        L2[(size_t)(by * 8 + y2) * R2 + bx * 16 + x2] = m;
    }
    __syncthreads();

    // L3: 8x4 per tile
    if (tid < 32) {
        int x3 = tid & 7, y3 = tid >> 3;         // 0..3
        float4 p00 = s2[(2*y3) * 16 + 2*x3];
        float4 p01 = s2[(2*y3) * 16 + 2*x3 + 1];
        float4 p10 = s2[(2*y3+1) * 16 + 2*x3];
        float4 p11 = s2[(2*y3+1) * 16 + 2*x3 + 1];
        float4 m = make_float4(0.25f * (p00.x + p01.x + p10.x + p11.x),
                               0.25f * (p00.y + p01.y + p10.y + p11.y),
                               0.25f * (p00.z + p01.z + p10.z + p11.z), 0.0f);
        int R3 = R1 >> 2;
        L3[(size_t)(by * 4 + y3) * R3 + bx * 8 + x3] = m;
    }
}

__global__ void __launch_bounds__(256) buildA(const float* __restrict__ t0,
                                              const float* __restrict__ t1) {
    __shared__ float4 s1[32 * 16];
    __shared__ float4 s2[16 * 8];
    int b = blockIdx.x, tid = threadIdx.x;
    if (b < 768) {                       // tex1: 6 faces x 128 tiles
        int f = b >> 7, q = b & 127;
        int bx = q & 7, by = q >> 3;     // by 0..15
        build_tile(t1 + (size_t)f * 512 * 512 * 3, 1536,
                   g_p1 + OFF1[1] + (size_t)f * 256 * 256, 256,
                   g_p1 + OFF1[2] + (size_t)f * 128 * 128,
                   g_p1 + OFF1[3] + (size_t)f * 64 * 64,
                   bx, by, tid, s1, s2);
    } else {                             // tex0: 6 faces x 8 tiles
        int j = b - 768;
        int f = j >> 3, q = j & 7;
        int bx = q & 1, by = q >> 1;     // by 0..3
        build_tile(t0 + (size_t)f * 128 * 128 * 3, 384,
                   g_p0 + OFF0[1] + (size_t)f * 64 * 64, 64,
                   g_p0 + OFF0[2] + (size_t)f * 32 * 32,
                   g_p0 + OFF0[3] + (size_t)f * 16 * 16,
                   bx, by, tid, s1, s2);
    }
}

// ---------------------------------------------------------------------------
// buildTail: per-face in-smem reduction of remaining levels (from L3 up).
// ---------------------------------------------------------------------------
__global__ void buildTail() {
    extern __shared__ float4 sm[];
    float4* A = sm;
    float4* Bb = sm + 4096;

    int b = blockIdx.x;
    float4* pyr; const int* offs; int Rsrc, lmax, f;
    if (b < 6) { f = b;     pyr = g_p1; offs = OFF1; Rsrc = 64; lmax = 9; }
    else       { f = b - 6; pyr = g_p0; offs = OFF0; Rsrc = 16; lmax = 7; }

    const float4* src = pyr + offs[3] + (size_t)f * Rsrc * Rsrc;
    for (int i = threadIdx.x; i < Rsrc * Rsrc; i += blockDim.x) A[i] = src[i];
    __syncthreads();

    int curR = Rsrc;
    for (int l = 4; l <= lmax; l++) {
        int R = curR >> 1;
        float4* dst_g = pyr + offs[l] + (size_t)f * R * R;
        for (int i = threadIdx.x; i < R * R; i += blockDim.x) {
            int x = i % R, y = i / R;
            const float4* p = A + (size_t)(2 * y) * curR + 2 * x;
            const float4* q = p + curR;
            float4 m = make_float4(
                0.25f * (p[0].x + p[1].x + q[0].x + q[1].x),
                0.25f * (p[0].y + p[1].y + q[0].y + q[1].y),
                0.25f * (p[0].z + p[1].z + q[0].z + q[1].z), 0.0f);
            Bb[i] = m;
            dst_g[i] = m;
        }
        __syncthreads();
        float4* tmp = A; A = Bb; Bb = tmp;
        curR = R;
    }
}

// ---------------------------------------------------------------------------
// Sampling helpers
// ---------------------------------------------------------------------------
struct TapIdx { int i00, i01, i10, i11; float w00, w01, w10, w11; };

__device__ __forceinline__ TapIdx tap_idx(int R, float u, float v) {
    float x = u * (float)R - 0.5f;
    float y = v * (float)R - 0.5f;
    float x0f = floorf(x), y0f = floorf(y);
    float fx = x - x0f, fy = y - y0f;
    int xi = (int)x0f, yi = (int)y0f;
    int x0 = min(max(xi, 0), R - 1);
    int x1 = min(max(xi + 1, 0), R - 1);
    int y0 = min(max(yi, 0), R - 1);
    int y1 = min(max(yi + 1, 0), R - 1);
    TapIdx t;
    t.i00 = y0 * R + x0; t.i01 = y0 * R + x1;
    t.i10 = y1 * R + x0; t.i11 = y1 * R + x1;
    t.w00 = (1.0f - fx) * (1.0f - fy);
    t.w01 = fx * (1.0f - fy);
    t.w10 = (1.0f - fx) * fy;
    t.w11 = fx * fy;
    return t;
}

__device__ __forceinline__ uint2 pack3(float x, float y, float z) {
    __half2 a = __floats2half2_rn(x, y);
    __half2 b = __floats2half2_rn(z, 0.0f);
    uint2 r;
    r.x = *reinterpret_cast<unsigned*>(&a);
    r.y = *reinterpret_cast<unsigned*>(&b);
    return r;
}

__device__ __forceinline__ float3 unpack3(uint2 r) {
    float2 xy = __half22float2(*reinterpret_cast<__half2*>(&r.x));
    float2 zw = __half22float2(*reinterpret_cast<__half2*>(&r.y));
    return make_float3(xy.x, xy.y, zw.x);
}

// bilinear from smem half4 (centered devs)
__device__ __forceinline__ float3 bil_sm(const uint2* __restrict__ b, int R,
                                         float u, float v) {
    TapIdx ti = tap_idx(R, u, v);
    float3 g00 = unpack3(b[ti.i00]);
    float3 g01 = unpack3(b[ti.i01]);
    float3 g10 = unpack3(b[ti.i10]);
    float3 g11 = unpack3(b[ti.i11]);
    float3 r;
    r.x = ti.w00 * g00.x + ti.w01 * g01.x + ti.w10 * g10.x + ti.w11 * g11.x;
    r.y = ti.w00 * g00.y + ti.w01 * g01.y + ti.w10 * g10.y + ti.w11 * g11.y;
    r.z = ti.w00 * g00.z + ti.w01 * g01.z + ti.w10 * g10.z + ti.w11 * g11.z;
    return r;
}

// bilinear from global float4 pyramid (cold levels)
__device__ __forceinline__ float3 bil4(const float4* __restrict__ t, int R,
                                       int face, float u, float v) {
    TapIdx ti = tap_idx(R, u, v);
    const float4* b = t + (size_t)face * R * R;
    float4 g00 = __ldg(b + ti.i00);
    float4 g01 = __ldg(b + ti.i01);
    float4 g10 = __ldg(b + ti.i10);
    float4 g11 = __ldg(b + ti.i11);
    float3 r;
    r.x = ti.w00 * g00.x + ti.w01 * g01.x + ti.w10 * g10.x + ti.w11 * g11.x;
    r.y = ti.w00 * g00.y + ti.w01 * g01.y + ti.w10 * g10.y + ti.w11 * g11.y;
    r.z = ti.w00 * g00.z + ti.w01 * g01.z + ti.w10 * g10.z + ti.w11 * g11.z;
    return r;
}

// coldest path: level 0 lives in the float3 input buffer (effectively never)
__device__ __forceinline__ float3 bil3(const float* __restrict__ t, int R,
                                       int face, float u, float v) {
    TapIdx ti = tap_idx(R, u, v);
    const float* b = t + (size_t)face * R * R * 3;
    const float* p00 = b + (size_t)ti.i00 * 3;
    const float* p01 = b + (size_t)ti.i01 * 3;
    const float* p10 = b + (size_t)ti.i10 * 3;
    const float* p11 = b + (size_t)ti.i11 * 3;
    float3 r;
    r.x = ti.w00 * p00[0] + ti.w01 * p01[0] + ti.w10 * p10[0] + ti.w11 * p11[0];
    r.y = ti.w00 * p00[1] + ti.w01 * p01[1] + ti.w10 * p10[1] + ti.w11 * p11[1];
    r.z = ti.w00 * p00[2] + ti.w01 * p01[2] + ti.w10 * p10[2] + ti.w11 * p11[2];
    return r;
}

// trilinear sample: hot levels from smem, cold levels from global
__device__ __forceinline__ float3 sample_pyr(
    const uint2* __restrict__ sm, const int* soff, int lmin, float center,
    const float* __restrict__ base3, const float4* __restrict__ pyr,
    const int* goff, int baseR, int lmax,
    float m, int face, float u, float v)
{
    m = fminf(m, (float)lmax);            // m >= 0 guaranteed by caller
    int l0 = (int)m;
    float f = m - (float)l0;
    float3 c;
    if (l0 >= lmin) {
        int R = baseR >> l0;
        c = bil_sm(sm + soff[l0] + face * R * R, R, u, v);
        c.x += center; c.y += center; c.z += center;
    } else if (l0 == 0) {
        c = bil3(base3, baseR, face, u, v);
    } else {
        c = bil4(pyr + goff[l0], baseR >> l0, face, u, v);
    }
    if (f > 0.0f) {
        int l1 = l0 + 1;
        float3 c1;
        if (l1 >= lmin) {
            int R = baseR >> l1;
            c1 = bil_sm(sm + soff[l1] + face * R * R, R, u, v);
            c1.x += center; c1.y += center; c1.z += center;
        } else {
            c1 = bil4(pyr + goff[l1], baseR >> l1, face, u, v);
        }
        float g = 1.0f - f;
        c.x = g * c.x + f * c1.x;
        c.y = g * c.y + f * c1.y;
        c.z = g * c.z + f * c1.z;
    }
    return c;
}

// ---------------------------------------------------------------------------
// Persistent sample kernel: hot pyramid cached in smem (half4, centered).
// ---------------------------------------------------------------------------
__global__ void __launch_bounds__(1024) sample_kernel(
                              const float* __restrict__ vd,
                              const float* __restrict__ sa,
                              const float* __restrict__ nu,
                              const float* __restrict__ t0,
                              const float* __restrict__ t1,
                              const float* __restrict__ pbr,
                              const float* __restrict__ pmul,
                              const float* __restrict__ pmb,
                              float* __restrict__ out, int n) {
    extern __shared__ uint2 smh[];       // [0,8190) tex1 L4-9, [8192,10238) tex0 L3-7
    int tid = threadIdx.x;

    // fill smem cache: contiguous hot ranges of both pyramids, centered
    {
        const float4* s1 = g_p1 + 516096;     // OFF1[4]
        for (int k = tid; k < 8190; k += 1024) {
            float4 v = s1[k];
            smh[k] = pack3(v.x + 1.0f, v.y + 1.0f, v.z + 1.0f);   // center -1
        }
        const float4* s0 = g_p0 + 30720;      // OFF0[3]
        for (int k = tid; k < 2046; k += 1024) {
            float4 v = s0[k];
            smh[8192 + k] = pack3(v.x + 2.0f, v.y + 2.0f, v.z + 2.0f); // center -2
        }
    }
    __syncthreads();

    float br  = fminf(fmaxf(pbr[0], -1.0f), 2.0f);
    float mul = pmul[0];
    float mb  = pmb[0];

    int stride = gridDim.x * blockDim.x;
    for (int i = blockIdx.x * blockDim.x + tid; i < n; i += stride) {
        float vx = vd[3 * (size_t)i + 0];
        float vy = vd[3 * (size_t)i + 1];
        float vz = vd[3 * (size_t)i + 2];
        float ax = fabsf(vx), ay = fabsf(vy), az = fabsf(vz);
        float ma = fmaxf(ax, fmaxf(ay, az));

        // log(saTexel) = -(log(ma) + 18*ln2);  1/(2 ln 4) = 0.36067376
        float mip = (sa[i] + __logf(ma) + 12.476649250079015f)
                    * 0.36067376022224085f + mb + 0.5f * nu[i];
        mip = fmaxf(mip, 0.0f);

        int face; float sc, tc, den;
        bool is_x = (ax >= ay) && (ax >= az);
        bool is_y = (!is_x) && (ay >= az);
        if (is_x)      { face = (vx >= 0.0f) ? 0 : 1; den = ax; sc = (vx >= 0.0f) ? -vz :  vz; tc = -vy; }
        else if (is_y) { face = (vy >= 0.0f) ? 2 : 3; den = ay; sc =  vx;                      tc = (vy >= 0.0f) ?  vz : -vz; }
        else           { face = (vz >= 0.0f) ? 4 : 5; den = az; sc = (vz >= 0.0f) ?  vx : -vx; tc = -vy; }
        float inv = __fdividef(1.0f, den);
        float u = 0.5f * (sc * inv + 1.0f);
        float v = 0.5f * (tc * inv + 1.0f);

        float3 s0 = sample_pyr(smh, SM0OFF, 3, -2.0f, t0, g_p0, OFF0,
                               128, 7, mip, face, u, v);
        float3 s1 = sample_pyr(smh, SM1OFF, 4, -1.0f, t1, g_p1, OFF1,
                               512, 9, mip, face, u, v);

        float ox = fminf(fmaxf(__expf(br + mul * (s0.x + s1.x)), 0.01f), 1000.0f);
        float oy = fminf(fmaxf(__expf(br + mul * (s0.y + s1.y)), 0.01f), 1000.0f);
        float oz = fminf(fmaxf(__expf(br + mul * (s0.z + s1.z)), 0.01f), 1000.0f);
        out[3 * (size_t)i + 0] = ox;
        out[3 * (size_t)i + 1] = oy;
        out[3 * (size_t)i + 2] = oz;
    }
}

extern "C" void kernel_launch(void* const* d_in, const int* in_sizes, int n_in,
                              void* d_out, int out_size) {
    const float* vd  = (const float*)d_in[0];  // viewdirs  [B,3]
    const float* sa  = (const float*)d_in[1];  // saSample  [B]
    const float* nu  = (const float*)d_in[2];  // noise_u   [B]
    const float* t0  = (const float*)d_in[3];  // bg_mat0   [1,6,128,128,3]
    const float* t1  = (const float*)d_in[4];  // bg_mat1   [1,6,512,512,3]
    const float* br  = (const float*)d_in[5];  // brightness scalar
    const float* mul = (const float*)d_in[6];  // mul scalar
    const float* mb  = (const float*)d_in[7];  // mipbias scalar
    int n = in_sizes[1];

    cudaFuncSetAttribute(buildTail, cudaFuncAttributeMaxDynamicSharedMemorySize,
                         81920);
    cudaFuncSetAttribute(sample_kernel,
                         cudaFuncAttributeMaxDynamicSharedMemorySize, 81904);

    buildA<<<816, 256>>>(t0, t1);              // L1-3 of both pyramids
    buildTail<<<12, 256, 81920>>>();           // L4+ per face
    sample_kernel<<<148, 1024, 81904>>>(vd, sa, nu, t0, t1, br, mul, mb,
                                        (float*)d_out, n);
}